// round 12
// baseline (speedup 1.0000x reference)
#include <cuda_runtime.h>
#include <cuda_fp16.h>
#include <stdint.h>

// StackedUnidirLSTMDecoder: B=64, L=4, H=1024, T=128
#define BB    64
#define LL    4
#define HH    1024
#define TT    128
#define GG    4096
#define NCTA  128
#define NTHR  1024            // 32 warps: (ks 0..7) x (wm 0..3), 8 warps/SMSP
#define NSTEP (TT * LL)       // 512
#define DYN_SMEM (8 * 4 * 16 * 32 * 4)   // s_part: 64 KB

// ---------------------------------------------------------------------------
// Device-global scratch
// ---------------------------------------------------------------------------
// W in mma B-fragment order fp16: [L][NCTA][kt=128][np=2][lane=32][8 halfs]
__device__ __align__(1024) __half g_Wp[(size_t)LL * NCTA * 128 * 512];
// A fragment blocks: g_A[p][l][mt=4][ktAll=128][512B]; ktAll<64 = X, >=64 = H
__device__ __align__(1024) __half g_A[2][LL][4 * 128 * 256];
__device__ float  g_bias[LL * GG];
__device__ unsigned g_bar_cnt, g_bar_gen;

// ---------------------------------------------------------------------------
// Grid barrier (proven since R4)
// ---------------------------------------------------------------------------
__device__ __forceinline__ void grid_sync() {
    __syncthreads();
    if (threadIdx.x == 0) {
        unsigned gen;
        asm volatile("ld.acquire.gpu.global.u32 %0, [%1];" : "=r"(gen) : "l"(&g_bar_gen));
        unsigned prev;
        asm volatile("atom.acq_rel.gpu.global.add.u32 %0, [%1], 1;"
                     : "=r"(prev) : "l"(&g_bar_cnt));
        if (prev == NCTA - 1) {
            asm volatile("st.relaxed.gpu.global.u32 [%0], %1;" :: "l"(&g_bar_cnt), "r"(0u));
            asm volatile("st.release.gpu.global.u32 [%0], %1;" :: "l"(&g_bar_gen), "r"(gen + 1u));
        } else {
            unsigned cur;
            do {
                asm volatile("ld.acquire.gpu.global.u32 %0, [%1];" : "=r"(cur) : "l"(&g_bar_gen));
            } while (cur == gen);
        }
    }
    __syncthreads();
}

__device__ __forceinline__ void mma16816(float* d,
                                         unsigned a0, unsigned a1, unsigned a2, unsigned a3,
                                         unsigned b0, unsigned b1) {
    asm volatile(
        "mma.sync.aligned.m16n8k16.row.col.f32.f16.f16.f32 "
        "{%0,%1,%2,%3},{%4,%5,%6,%7},{%8,%9},{%0,%1,%2,%3};\n"
        : "+f"(d[0]), "+f"(d[1]), "+f"(d[2]), "+f"(d[3])
        : "r"(a0), "r"(a1), "r"(a2), "r"(a3), "r"(b0), "r"(b1));
}
__device__ __forceinline__ float sigm(float v) { return 1.0f / (1.0f + __expf(-v)); }
__device__ __forceinline__ float tanh_fast(float v) {
    return 2.0f / (1.0f + __expf(-2.0f * v)) - 1.0f;
}

// ---------------------------------------------------------------------------
// Single persistent kernel: phase0 pack W, phase1 init A/bias, phase2 run.
// CTA c owns gate cols {g*1024+j : j in [8c,8c+8)}.
// GEMM: warp (ks 0..7, wm 0..3) = m-tile wm, k-tiles [16ks, 16ks+16).
// All 32 warps deposit partials (64KB dynamic SMEM); threads 0..511 each
// finalize ONE cell (register-resident c), summing 8 k-partials per gate.
// ---------------------------------------------------------------------------
__global__ void __launch_bounds__(NTHR, 1)
lstm_main(const float* __restrict__ x,
          const float* __restrict__ h0,
          const float* __restrict__ c0,
          const float* __restrict__ Wih,
          const float* __restrict__ Whh,
          const float* __restrict__ b_ih,
          const float* __restrict__ b_hh,
          float* __restrict__ out) {
    const int cta  = blockIdx.x;
    const int tid  = threadIdx.x;
    const int w    = tid >> 5;
    const int lane = tid & 31;
    const int ks   = w >> 2;          // 0..7
    const int wm   = w & 3;

    extern __shared__ float s_part[];  // [ks(8)][wm(4)][g*4+ci(16)][lane(32)]

    // ---------------- phase 0: pack W into fragment order -------------------
    for (int v = cta * NTHR + tid; v < LL * NCTA * 128 * 32; v += NCTA * NTHR) {
        int plane = v & 31;
        int pkt   = (v >> 5) & 127;
        int pcta  = (v >> 12) & 127;
        int pl    = v >> 19;
        int c8 = plane >> 2;
        int kq = (plane & 3) * 2;
        #pragma unroll
        for (int np = 0; np < 2; np++)
            #pragma unroll
            for (int ntl = 0; ntl < 2; ntl++) {
                int nt = np * 2 + ntl;
                int n  = nt * 1024 + pcta * 8 + c8;
                __half vv[4];
                #pragma unroll
                for (int e = 0; e < 4; e++) {
                    int k = pkt * 16 + kq + (e & 1) + 8 * (e >> 1);
                    float wv = (k < HH) ? Wih[((size_t)pl * GG + n) * HH + k]
                                        : Whh[((size_t)pl * GG + n) * HH + (k - HH)];
                    vv[e] = __float2half(wv);
                }
                size_t off = ((((size_t)(pl * NCTA + pcta) * 128 + pkt) * 2 + np) * 32
                              + plane) * 8 + ntl * 4;
                *(uint2*)&g_Wp[off] = *(uint2*)vv;
            }
    }

    // ---------------- phase 1: init A (x, h0) + biases ----------------------
    for (int v = cta * NTHR + tid; v < LL * BB * HH; v += NCTA * NTHR) {
        if (v < LL * GG) g_bias[v] = b_ih[v] + b_hh[v];
        int k = v & (HH - 1);
        int r = (v >> 10) & (BB - 1);
        int l = v >> 16;
        int mt    = r >> 4;
        int lane2 = (r & 7) * 4 + ((k & 7) >> 1);
        int reg   = ((r & 15) >> 3) + 2 * ((k & 15) >> 3);
        int inblk = lane2 * 8 + reg * 2 + (k & 1);
        g_A[0][l][(mt * 128 + 64 + (k >> 4)) * 256 + inblk] = __float2half(h0[v]);
        if (l == 0)
            g_A[0][0][(mt * 128 + (k >> 4)) * 256 + inblk] = __float2half(x[r * HH + k]);
    }
    grid_sync();

    // ---------------- per-thread cell ownership (threads 0..511) ------------
    const int own   = tid < 512;
    const int w2    = (tid >> 5) & 15;            // owning-warp index 0..15
    const int ks2   = w2 >> 2;                    // 0..3
    const int wm2   = w2 & 3;
    const int qrow2 = lane >> 1;                  // 0..15
    const int jj    = (lane & 1) * 4 + ks2;       // 0..7
    const int qrowp = qrow2 & 7;
    const int hh2   = qrow2 >> 3;
    const int tqp   = jj >> 1;
    const int u     = jj & 1;
    const int lanep = qrowp * 4 + tqp;
    const int di    = hh2 * 2 + u;
    const int r_own = wm2 * 16 + qrow2;
    const int j_own = cta * 8 + jj;

    float bias[LL][4], creg[LL];
    if (own) {
        #pragma unroll
        for (int l = 0; l < LL; l++) {
            #pragma unroll
            for (int g = 0; g < 4; g++)
                bias[l][g] = g_bias[l * GG + g * 1024 + j_own];
            creg[l] = c0[((size_t)l * BB + r_own) * HH + j_own];
        }
    }

    const char* __restrict__ Wcta = (const char*)g_Wp + (size_t)cta * 131072;
    const int aoff = (wm * 128 + ks * 16) * 512 + lane * 16;
    const int woff = (ks * 16) * 1024 + lane * 16;
    const int inblk_own = lanep * 16 + (cta & 1) * 8 + hh2 * 4 + u * 2;
    float* sp_dep = s_part + ((ks * 4 + wm) * 16) * 32 + lane;
    const float* sp_red = s_part + (wm2 * 16) * 32 + lanep;

    // ---------------- phase 2: 512 sequential cell-steps --------------------
    for (int s = 0; s < NSTEP; s++) {
        const int l = s & 3;
        const int t = s >> 2;
        const int p = t & 1;

        const char* Ab = (const char*)&g_A[p][l][0] + aoff;
        const char* Wb = Wcta + (size_t)l * NCTA * 131072 + woff;

        float acc[4][4];
        #pragma unroll
        for (int a = 0; a < 4; a++)
            #pragma unroll
            for (int b = 0; b < 4; b++) acc[a][b] = 0.0f;

        #pragma unroll 2
        for (int kk = 0; kk < 16; kk++) {
            uint4 a   = __ldcg((const uint4*)(Ab + (size_t)kk * 512));
            uint4 w01 = *(const uint4*)(Wb + (size_t)kk * 1024);
            uint4 w23 = *(const uint4*)(Wb + (size_t)kk * 1024 + 512);
            mma16816(acc[0], a.x, a.y, a.z, a.w, w01.x, w01.y);
            mma16816(acc[1], a.x, a.y, a.z, a.w, w01.z, w01.w);
            mma16816(acc[2], a.x, a.y, a.z, a.w, w23.x, w23.y);
            mma16816(acc[3], a.x, a.y, a.z, a.w, w23.z, w23.w);
        }

        // all 32 warps deposit partials
        #pragma unroll
        for (int g = 0; g < 4; g++)
            #pragma unroll
            for (int ci = 0; ci < 4; ci++)
                sp_dep[(g * 4 + ci) * 32] = acc[g][ci];
        __syncthreads();

        // distributed reduce + cell update: threads 0..511, one cell each
        if (own) {
            float gate[4];
            #pragma unroll
            for (int g = 0; g < 4; g++) {
                float sum = 0.0f;
                #pragma unroll
                for (int ps = 0; ps < 8; ps++)
                    sum += sp_red[((ps * 4) * 16 + g * 4 + di) * 32];
                gate[g] = sum;
            }

            float gi = gate[0] + bias[l][0];
            float gf = gate[1] + bias[l][1];
            float gg = gate[2] + bias[l][2];
            float go = gate[3] + bias[l][3];
            float ig = sigm(gi), fg = sigm(gf), og = sigm(go);
            float gt = tanh_fast(gg);
            float cn = fg * creg[l] + ig * gt;
            creg[l] = cn;
            float hn = og * tanh_fast(cn);
            __half hv = __float2half(hn);

            char* dstH = (char*)&g_A[p ^ 1][l][0];
            char* dstX = (l < LL - 1) ? (char*)&g_A[p][l + 1][0]
                                      : (char*)&g_A[p ^ 1][0][0];   // y feedback
            *(__half*)(dstH + (size_t)(wm2 * 128 + 64 + (cta >> 1)) * 512 + inblk_own) = hv;
            *(__half*)(dstX + (size_t)(wm2 * 128 + (cta >> 1)) * 512 + inblk_own) = hv;
            if (l == LL - 1)
                out[((size_t)r_own * TT + t) * HH + j_own] = hn;
        }

        grid_sync();
    }
}

// ---------------------------------------------------------------------------
// kernel_launch: ONE persistent kernel (single graph node)
// inputs: x, h0, c0, W_ih, W_hh, b_ih, b_hh, seq_len
// ---------------------------------------------------------------------------
extern "C" void kernel_launch(void* const* d_in, const int* in_sizes, int n_in,
                              void* d_out, int out_size) {
    const float* x   = (const float*)d_in[0];
    const float* h0  = (const float*)d_in[1];
    const float* c0  = (const float*)d_in[2];
    const float* Wih = (const float*)d_in[3];
    const float* Whh = (const float*)d_in[4];
    const float* bih = (const float*)d_in[5];
    const float* bhh = (const float*)d_in[6];
    float* out = (float*)d_out;

    cudaFuncSetAttribute(lstm_main,
                         cudaFuncAttributeMaxDynamicSharedMemorySize, DYN_SMEM);
    lstm_main<<<NCTA, NTHR, DYN_SMEM>>>(x, h0, c0, Wih, Whh, bih, bhh, out);
}

// round 13
// speedup vs baseline: 1.2078x; 1.2078x over previous
#include <cuda_runtime.h>
#include <cuda_fp16.h>
#include <stdint.h>

// StackedUnidirLSTMDecoder: B=64, L=4, H=1024, T=128
#define BB    64
#define LL    4
#define HH    1024
#define TT    128
#define GG    4096
#define NCTA  128
#define NTHR  512             // 16 warps: (ks 0..7) x (mh 0..1)
#define NSTEP (TT * LL)       // 512
#define DYN_SMEM (8 * 4 * 16 * 32 * 4)   // s_part[ks][mt][g*4+ci][lane] = 64 KB

// ---------------------------------------------------------------------------
// Device-global scratch
// ---------------------------------------------------------------------------
// W in mma B-fragment order fp16: [L][NCTA][kt=128][np=2][lane=32][8 halfs]
__device__ __align__(1024) __half g_Wp[(size_t)LL * NCTA * 128 * 512];
// A fragment blocks: g_A[p][l][mt=4][ktAll=128][512B]; ktAll<64 = X, >=64 = H
__device__ __align__(1024) __half g_A[2][LL][4 * 128 * 256];
__device__ float  g_bias[LL * GG];
__device__ unsigned g_bar_cnt, g_bar_gen;

// ---------------------------------------------------------------------------
// Grid barrier (proven since R4)
// ---------------------------------------------------------------------------
__device__ __forceinline__ void grid_sync() {
    __syncthreads();
    if (threadIdx.x == 0) {
        unsigned gen;
        asm volatile("ld.acquire.gpu.global.u32 %0, [%1];" : "=r"(gen) : "l"(&g_bar_gen));
        unsigned prev;
        asm volatile("atom.acq_rel.gpu.global.add.u32 %0, [%1], 1;"
                     : "=r"(prev) : "l"(&g_bar_cnt));
        if (prev == NCTA - 1) {
            asm volatile("st.relaxed.gpu.global.u32 [%0], %1;" :: "l"(&g_bar_cnt), "r"(0u));
            asm volatile("st.release.gpu.global.u32 [%0], %1;" :: "l"(&g_bar_gen), "r"(gen + 1u));
        } else {
            unsigned cur;
            do {
                asm volatile("ld.acquire.gpu.global.u32 %0, [%1];" : "=r"(cur) : "l"(&g_bar_gen));
            } while (cur == gen);
        }
    }
    __syncthreads();
}

__device__ __forceinline__ void mma16816(float* d,
                                         unsigned a0, unsigned a1, unsigned a2, unsigned a3,
                                         unsigned b0, unsigned b1) {
    asm volatile(
        "mma.sync.aligned.m16n8k16.row.col.f32.f16.f16.f32 "
        "{%0,%1,%2,%3},{%4,%5,%6,%7},{%8,%9},{%0,%1,%2,%3};\n"
        : "+f"(d[0]), "+f"(d[1]), "+f"(d[2]), "+f"(d[3])
        : "r"(a0), "r"(a1), "r"(a2), "r"(a3), "r"(b0), "r"(b1));
}
__device__ __forceinline__ float sigm(float v) { return 1.0f / (1.0f + __expf(-v)); }
__device__ __forceinline__ float tanh_fast(float v) {
    return 2.0f / (1.0f + __expf(-2.0f * v)) - 1.0f;
}

// ---------------------------------------------------------------------------
// Single persistent kernel: phase0 pack W, phase1 init A/bias, phase2 run.
// CTA c owns gate cols {g*1024+j : j in [8c,8c+8)}.
// GEMM: warp (ks 0..7, mh 0..1): kt in [16ks,16ks+16), m-tiles {2mh, 2mh+1}.
// W fragments are loaded ONCE per CTA (was 4x) -> L1tex wavefronts -33%.
// All warps deposit partials (64KB dyn SMEM); each thread finalizes ONE cell.
// ---------------------------------------------------------------------------
__global__ void __launch_bounds__(NTHR, 1)
lstm_main(const float* __restrict__ x,
          const float* __restrict__ h0,
          const float* __restrict__ c0,
          const float* __restrict__ Wih,
          const float* __restrict__ Whh,
          const float* __restrict__ b_ih,
          const float* __restrict__ b_hh,
          float* __restrict__ out) {
    const int cta  = blockIdx.x;
    const int tid  = threadIdx.x;
    const int w    = tid >> 5;
    const int lane = tid & 31;
    const int ks   = w >> 1;          // 0..7  (k-tile group)
    const int mh   = w & 1;           // 0..1  (m-tile pair)

    extern __shared__ float s_part[];  // [ks(8)][mt(4)][g*4+ci(16)][lane(32)]

    // ---------------- phase 0: pack W into fragment order -------------------
    for (int v = cta * NTHR + tid; v < LL * NCTA * 128 * 32; v += NCTA * NTHR) {
        int plane = v & 31;
        int pkt   = (v >> 5) & 127;
        int pcta  = (v >> 12) & 127;
        int pl    = v >> 19;
        int c8 = plane >> 2;
        int kq = (plane & 3) * 2;
        #pragma unroll
        for (int np = 0; np < 2; np++)
            #pragma unroll
            for (int ntl = 0; ntl < 2; ntl++) {
                int nt = np * 2 + ntl;
                int n  = nt * 1024 + pcta * 8 + c8;
                __half vv[4];
                #pragma unroll
                for (int e = 0; e < 4; e++) {
                    int k = pkt * 16 + kq + (e & 1) + 8 * (e >> 1);
                    float wv = (k < HH) ? Wih[((size_t)pl * GG + n) * HH + k]
                                        : Whh[((size_t)pl * GG + n) * HH + (k - HH)];
                    vv[e] = __float2half(wv);
                }
                size_t off = ((((size_t)(pl * NCTA + pcta) * 128 + pkt) * 2 + np) * 32
                              + plane) * 8 + ntl * 4;
                *(uint2*)&g_Wp[off] = *(uint2*)vv;
            }
    }

    // ---------------- phase 1: init A (x, h0) + biases ----------------------
    for (int v = cta * NTHR + tid; v < LL * BB * HH; v += NCTA * NTHR) {
        if (v < LL * GG) g_bias[v] = b_ih[v] + b_hh[v];
        int k = v & (HH - 1);
        int r = (v >> 10) & (BB - 1);
        int l = v >> 16;
        int mt    = r >> 4;
        int lane2 = (r & 7) * 4 + ((k & 7) >> 1);
        int reg   = ((r & 15) >> 3) + 2 * ((k & 15) >> 3);
        int inblk = lane2 * 8 + reg * 2 + (k & 1);
        g_A[0][l][(mt * 128 + 64 + (k >> 4)) * 256 + inblk] = __float2half(h0[v]);
        if (l == 0)
            g_A[0][0][(mt * 128 + (k >> 4)) * 256 + inblk] = __float2half(x[r * HH + k]);
    }
    grid_sync();

    // ---------------- per-thread cell ownership (all 512 threads) -----------
    const int ks2   = w >> 2;                     // 0..3 (ownership grid)
    const int wm2   = w & 3;
    const int qrow2 = lane >> 1;                  // 0..15
    const int jj    = (lane & 1) * 4 + ks2;       // 0..7
    const int qrowp = qrow2 & 7;
    const int hh2   = qrow2 >> 3;
    const int tqp   = jj >> 1;
    const int u     = jj & 1;
    const int lanep = qrowp * 4 + tqp;
    const int di    = hh2 * 2 + u;
    const int r_own = wm2 * 16 + qrow2;
    const int j_own = cta * 8 + jj;

    float bias[LL][4], creg[LL];
    #pragma unroll
    for (int l = 0; l < LL; l++) {
        #pragma unroll
        for (int g = 0; g < 4; g++)
            bias[l][g] = g_bias[l * GG + g * 1024 + j_own];
        creg[l] = c0[((size_t)l * BB + r_own) * HH + j_own];
    }

    const char* __restrict__ Wcta = (const char*)g_Wp + (size_t)cta * 131072;
    const int aoff0 = ((mh * 2) * 128 + ks * 16) * 512 + lane * 16;  // mt = 2mh
    const int woff  = (ks * 16) * 1024 + lane * 16;
    const int inblk_own = lanep * 16 + (cta & 1) * 8 + hh2 * 4 + u * 2;
    float* sp_dep = s_part + ((ks * 4 + mh * 2) * 16) * 32 + lane;   // mt=2mh base
    const float* sp_red = s_part + (wm2 * 16) * 32 + lanep;

    // ---------------- phase 2: 512 sequential cell-steps --------------------
    for (int s = 0; s < NSTEP; s++) {
        const int l = s & 3;
        const int t = s >> 2;
        const int p = t & 1;

        const char* Ab0 = (const char*)&g_A[p][l][0] + aoff0;
        const char* Ab1 = Ab0 + 128 * 512;                 // mt = 2mh+1
        const char* Wb  = Wcta + (size_t)l * NCTA * 131072 + woff;

        float acc[2][4][4];
        #pragma unroll
        for (int i = 0; i < 2; i++)
            #pragma unroll
            for (int a = 0; a < 4; a++)
                #pragma unroll
                for (int b = 0; b < 4; b++) acc[i][a][b] = 0.0f;

        #pragma unroll 2
        for (int kk = 0; kk < 16; kk++) {
            uint4 a0  = __ldcg((const uint4*)(Ab0 + (size_t)kk * 512));
            uint4 a1  = __ldcg((const uint4*)(Ab1 + (size_t)kk * 512));
            uint4 w01 = *(const uint4*)(Wb + (size_t)kk * 1024);
            uint4 w23 = *(const uint4*)(Wb + (size_t)kk * 1024 + 512);
            mma16816(acc[0][0], a0.x, a0.y, a0.z, a0.w, w01.x, w01.y);
            mma16816(acc[1][0], a1.x, a1.y, a1.z, a1.w, w01.x, w01.y);
            mma16816(acc[0][1], a0.x, a0.y, a0.z, a0.w, w01.z, w01.w);
            mma16816(acc[1][1], a1.x, a1.y, a1.z, a1.w, w01.z, w01.w);
            mma16816(acc[0][2], a0.x, a0.y, a0.z, a0.w, w23.x, w23.y);
            mma16816(acc[1][2], a1.x, a1.y, a1.z, a1.w, w23.x, w23.y);
            mma16816(acc[0][3], a0.x, a0.y, a0.z, a0.w, w23.z, w23.w);
            mma16816(acc[1][3], a1.x, a1.y, a1.z, a1.w, w23.z, w23.w);
        }

        // deposit partials: warp (ks, mh) -> s_part[ks][2mh + i][g*4+ci][lane]
        #pragma unroll
        for (int i = 0; i < 2; i++)
            #pragma unroll
            for (int g = 0; g < 4; g++)
                #pragma unroll
                for (int ci = 0; ci < 4; ci++)
                    sp_dep[(i * 16 + g * 4 + ci) * 32] = acc[i][g][ci];
        __syncthreads();

        // distributed reduce + cell update: each thread finalizes ONE cell
        float gate[4];
        #pragma unroll
        for (int g = 0; g < 4; g++) {
            float sum = 0.0f;
            #pragma unroll
            for (int ps = 0; ps < 8; ps++)
                sum += sp_red[((ps * 4) * 16 + g * 4 + di) * 32];
            gate[g] = sum;
        }

        float gi = gate[0] + bias[l][0];
        float gf = gate[1] + bias[l][1];
        float gg = gate[2] + bias[l][2];
        float go = gate[3] + bias[l][3];
        float ig = sigm(gi), fg = sigm(gf), og = sigm(go);
        float gt = tanh_fast(gg);
        float cn = fg * creg[l] + ig * gt;
        creg[l] = cn;
        float hn = og * tanh_fast(cn);
        __half hv = __float2half(hn);

        char* dstH = (char*)&g_A[p ^ 1][l][0];
        char* dstX = (l < LL - 1) ? (char*)&g_A[p][l + 1][0]
                                  : (char*)&g_A[p ^ 1][0][0];   // y feedback
        *(__half*)(dstH + (size_t)(wm2 * 128 + 64 + (cta >> 1)) * 512 + inblk_own) = hv;
        *(__half*)(dstX + (size_t)(wm2 * 128 + (cta >> 1)) * 512 + inblk_own) = hv;
        if (l == LL - 1)
            out[((size_t)r_own * TT + t) * HH + j_own] = hn;

        grid_sync();
    }
}

// ---------------------------------------------------------------------------
// kernel_launch: ONE persistent kernel (single graph node)
// inputs: x, h0, c0, W_ih, W_hh, b_ih, b_hh, seq_len
// ---------------------------------------------------------------------------
extern "C" void kernel_launch(void* const* d_in, const int* in_sizes, int n_in,
                              void* d_out, int out_size) {
    const float* x   = (const float*)d_in[0];
    const float* h0  = (const float*)d_in[1];
    const float* c0  = (const float*)d_in[2];
    const float* Wih = (const float*)d_in[3];
    const float* Whh = (const float*)d_in[4];
    const float* bih = (const float*)d_in[5];
    const float* bhh = (const float*)d_in[6];
    float* out = (float*)d_out;

    cudaFuncSetAttribute(lstm_main,
                         cudaFuncAttributeMaxDynamicSharedMemorySize, DYN_SMEM);
    lstm_main<<<NCTA, NTHR, DYN_SMEM>>>(x, h0, c0, Wih, Whh, bih, bhh, out);
}

// round 14
// speedup vs baseline: 1.2626x; 1.0454x over previous
#include <cuda_runtime.h>
#include <cuda_fp16.h>
#include <stdint.h>

// StackedUnidirLSTMDecoder: B=64, L=4, H=1024, T=128
#define BB    64
#define LL    4
#define HH    1024
#define TT    128
#define GG    4096
#define NCTA  128
#define NTHR  512             // 16 warps: (ks 0..7) x (mh 0..1)
#define NSTEP (TT * LL)       // 512
#define WBYTES 131072         // per-(l,cta) W slice: 128 kt x 1024 B
#define SPART_OFF  WBYTES                  // s_part after W buffer
#define MBAR_OFF  (WBYTES + 65536)         // mbarrier after s_part
#define DYN_SMEM  (WBYTES + 65536 + 64)    // 196672 B

// ---------------------------------------------------------------------------
// Device-global scratch
// ---------------------------------------------------------------------------
// W in mma B-fragment order fp16: [L][NCTA][kt=128][np=2][lane=32][8 halfs]
__device__ __align__(1024) __half g_Wp[(size_t)LL * NCTA * 128 * 512];
// A fragment blocks: g_A[p][l][mt=4][ktAll=128][512B]; ktAll<64 = X, >=64 = H
__device__ __align__(1024) __half g_A[2][LL][4 * 128 * 256];
__device__ float  g_bias[LL * GG];
__device__ unsigned g_bar_cnt, g_bar_gen;

// ---------------------------------------------------------------------------
// Grid barrier (proven since R4)
// ---------------------------------------------------------------------------
__device__ __forceinline__ void grid_sync() {
    __syncthreads();
    if (threadIdx.x == 0) {
        unsigned gen;
        asm volatile("ld.acquire.gpu.global.u32 %0, [%1];" : "=r"(gen) : "l"(&g_bar_gen));
        unsigned prev;
        asm volatile("atom.acq_rel.gpu.global.add.u32 %0, [%1], 1;"
                     : "=r"(prev) : "l"(&g_bar_cnt));
        if (prev == NCTA - 1) {
            asm volatile("st.relaxed.gpu.global.u32 [%0], %1;" :: "l"(&g_bar_cnt), "r"(0u));
            asm volatile("st.release.gpu.global.u32 [%0], %1;" :: "l"(&g_bar_gen), "r"(gen + 1u));
        } else {
            unsigned cur;
            do {
                asm volatile("ld.acquire.gpu.global.u32 %0, [%1];" : "=r"(cur) : "l"(&g_bar_gen));
            } while (cur == gen);
        }
    }
    __syncthreads();
}

// ---------------------------------------------------------------------------
// mbarrier / bulk helpers (CTA-local)
// ---------------------------------------------------------------------------
__device__ __forceinline__ void mbar_init(uint32_t a, uint32_t cnt) {
    asm volatile("mbarrier.init.shared.b64 [%0], %1;" :: "r"(a), "r"(cnt) : "memory");
}
__device__ __forceinline__ void mbar_expect_tx(uint32_t a, uint32_t bytes) {
    asm volatile("mbarrier.arrive.expect_tx.shared.b64 _, [%0], %1;"
                 :: "r"(a), "r"(bytes) : "memory");
}
__device__ __forceinline__ void mbar_wait_acq(uint32_t a, uint32_t ph) {
    uint32_t done;
    do {
        asm volatile(
            "{\n\t.reg .pred p;\n\t"
            "mbarrier.try_wait.parity.acquire.cta.shared::cta.b64 p, [%1], %2, 0x989680;\n\t"
            "selp.b32 %0, 1, 0, p;\n\t}"
            : "=r"(done) : "r"(a), "r"(ph) : "memory");
    } while (!done);
}
__device__ __forceinline__ void bulk_g2s(uint32_t dst, const void* src, uint32_t bytes,
                                         uint32_t bar) {
    asm volatile(
        "cp.async.bulk.shared::cta.global.mbarrier::complete_tx::bytes "
        "[%0], [%1], %2, [%3];"
        :: "r"(dst), "l"(src), "r"(bytes), "r"(bar) : "memory");
}

__device__ __forceinline__ void mma16816(float* d,
                                         unsigned a0, unsigned a1, unsigned a2, unsigned a3,
                                         unsigned b0, unsigned b1) {
    asm volatile(
        "mma.sync.aligned.m16n8k16.row.col.f32.f16.f16.f32 "
        "{%0,%1,%2,%3},{%4,%5,%6,%7},{%8,%9},{%0,%1,%2,%3};\n"
        : "+f"(d[0]), "+f"(d[1]), "+f"(d[2]), "+f"(d[3])
        : "r"(a0), "r"(a1), "r"(a2), "r"(a3), "r"(b0), "r"(b1));
}
__device__ __forceinline__ float sigm(float v) { return 1.0f / (1.0f + __expf(-v)); }
__device__ __forceinline__ float tanh_fast(float v) {
    return 2.0f / (1.0f + __expf(-2.0f * v)) - 1.0f;
}

// ---------------------------------------------------------------------------
// Single persistent kernel.
// Per step: GEMM reads A via LDG.cg (16/warp) and W via LDS.128 from a
// single 128KB SMEM buffer that was prefetched (cp.async.bulk, 4x32KB)
// DURING the previous step's reduce/stores/grid-barrier window.
// GEMM: warp (ks 0..7, mh 0..1): kt in [16ks,16ks+16), m-tiles {2mh,2mh+1}.
// Distributed reduce: each of the 512 threads finalizes ONE cell.
// ---------------------------------------------------------------------------
__global__ void __launch_bounds__(NTHR, 1)
lstm_main(const float* __restrict__ x,
          const float* __restrict__ h0,
          const float* __restrict__ c0,
          const float* __restrict__ Wih,
          const float* __restrict__ Whh,
          const float* __restrict__ b_ih,
          const float* __restrict__ b_hh,
          float* __restrict__ out) {
    extern __shared__ __align__(1024) char dsm[];
    uint32_t sbase;
    asm("{\n\t.reg .u64 t;\n\tcvta.to.shared.u64 t, %1;\n\tcvt.u32.u64 %0, t;\n\t}"
        : "=r"(sbase) : "l"(dsm));
    float* s_part = (float*)(dsm + SPART_OFF);   // [ks8][mt4][16][32]
    const uint32_t mbar = sbase + MBAR_OFF;

    const int cta  = blockIdx.x;
    const int tid  = threadIdx.x;
    const int w    = tid >> 5;
    const int lane = tid & 31;
    const int ks   = w >> 1;          // 0..7  (k-tile group)
    const int mh   = w & 1;           // 0..1  (m-tile pair)

    // ---------------- phase 0: pack W into fragment order -------------------
    for (int v = cta * NTHR + tid; v < LL * NCTA * 128 * 32; v += NCTA * NTHR) {
        int plane = v & 31;
        int pkt   = (v >> 5) & 127;
        int pcta  = (v >> 12) & 127;
        int pl    = v >> 19;
        int c8 = plane >> 2;
        int kq = (plane & 3) * 2;
        #pragma unroll
        for (int np = 0; np < 2; np++)
            #pragma unroll
            for (int ntl = 0; ntl < 2; ntl++) {
                int nt = np * 2 + ntl;
                int n  = nt * 1024 + pcta * 8 + c8;
                __half vv[4];
                #pragma unroll
                for (int e = 0; e < 4; e++) {
                    int k = pkt * 16 + kq + (e & 1) + 8 * (e >> 1);
                    float wv = (k < HH) ? Wih[((size_t)pl * GG + n) * HH + k]
                                        : Whh[((size_t)pl * GG + n) * HH + (k - HH)];
                    vv[e] = __float2half(wv);
                }
                size_t off = ((((size_t)(pl * NCTA + pcta) * 128 + pkt) * 2 + np) * 32
                              + plane) * 8 + ntl * 4;
                *(uint2*)&g_Wp[off] = *(uint2*)vv;
            }
    }

    // ---------------- phase 1: init A (x, h0) + biases ----------------------
    for (int v = cta * NTHR + tid; v < LL * BB * HH; v += NCTA * NTHR) {
        if (v < LL * GG) g_bias[v] = b_ih[v] + b_hh[v];
        int k = v & (HH - 1);
        int r = (v >> 10) & (BB - 1);
        int l = v >> 16;
        int mt    = r >> 4;
        int lane2 = (r & 7) * 4 + ((k & 7) >> 1);
        int reg   = ((r & 15) >> 3) + 2 * ((k & 15) >> 3);
        int inblk = lane2 * 8 + reg * 2 + (k & 1);
        g_A[0][l][(mt * 128 + 64 + (k >> 4)) * 256 + inblk] = __float2half(h0[v]);
        if (l == 0)
            g_A[0][0][(mt * 128 + (k >> 4)) * 256 + inblk] = __float2half(x[r * HH + k]);
    }
    if (tid == 0) mbar_init(mbar, 1);
    grid_sync();   // W pack globally visible; mbar initialized

    const char* __restrict__ Wcta = (const char*)g_Wp + (size_t)cta * WBYTES;

    // prologue: prefetch W for step 0 (layer 0)
    if (tid == 0) {
        asm volatile("fence.proxy.async;" ::: "memory");
        mbar_expect_tx(mbar, WBYTES);
        #pragma unroll
        for (int c = 0; c < 4; c++)
            bulk_g2s(sbase + c * 32768, Wcta + c * 32768, 32768, mbar);
    }

    // ---------------- per-thread cell ownership (all 512 threads) -----------
    const int ks2   = w >> 2;
    const int wm2   = w & 3;
    const int qrow2 = lane >> 1;
    const int jj    = (lane & 1) * 4 + ks2;
    const int qrowp = qrow2 & 7;
    const int hh2   = qrow2 >> 3;
    const int tqp   = jj >> 1;
    const int u     = jj & 1;
    const int lanep = qrowp * 4 + tqp;
    const int di    = hh2 * 2 + u;
    const int r_own = wm2 * 16 + qrow2;
    const int j_own = cta * 8 + jj;

    float bias[LL][4], creg[LL];
    #pragma unroll
    for (int l = 0; l < LL; l++) {
        #pragma unroll
        for (int g = 0; g < 4; g++)
            bias[l][g] = g_bias[l * GG + g * 1024 + j_own];
        creg[l] = c0[((size_t)l * BB + r_own) * HH + j_own];
    }

    const int aoff0 = ((mh * 2) * 128 + ks * 16) * 512 + lane * 16;  // mt = 2mh
    const uint32_t wsm0 = sbase + (uint32_t)((ks * 16) * 1024 + lane * 16);
    const int inblk_own = lanep * 16 + (cta & 1) * 8 + hh2 * 4 + u * 2;
    float* sp_dep = s_part + ((ks * 4 + mh * 2) * 16) * 32 + lane;
    const float* sp_red = s_part + (wm2 * 16) * 32 + lanep;

    // ---------------- phase 2: 512 sequential cell-steps --------------------
    for (int s = 0; s < NSTEP; s++) {
        const int l = s & 3;
        const int t = s >> 2;
        const int p = t & 1;

        mbar_wait_acq(mbar, s & 1);   // W(s) resident in SMEM (usually already)

        const char* Ab0 = (const char*)&g_A[p][l][0] + aoff0;
        const char* Ab1 = Ab0 + 128 * 512;                 // mt = 2mh+1

        float acc[2][4][4];
        #pragma unroll
        for (int i = 0; i < 2; i++)
            #pragma unroll
            for (int a = 0; a < 4; a++)
                #pragma unroll
                for (int b = 0; b < 4; b++) acc[i][a][b] = 0.0f;

        #pragma unroll 4
        for (int kk = 0; kk < 16; kk++) {
            uint4 a0 = __ldcg((const uint4*)(Ab0 + (size_t)kk * 512));
            uint4 a1 = __ldcg((const uint4*)(Ab1 + (size_t)kk * 512));
            uint4 w01, w23;
            asm volatile("ld.shared.v4.u32 {%0,%1,%2,%3}, [%4];"
                         : "=r"(w01.x), "=r"(w01.y), "=r"(w01.z), "=r"(w01.w)
                         : "r"(wsm0 + (uint32_t)(kk * 1024)));
            asm volatile("ld.shared.v4.u32 {%0,%1,%2,%3}, [%4];"
                         : "=r"(w23.x), "=r"(w23.y), "=r"(w23.z), "=r"(w23.w)
                         : "r"(wsm0 + (uint32_t)(kk * 1024 + 512)));
            mma16816(acc[0][0], a0.x, a0.y, a0.z, a0.w, w01.x, w01.y);
            mma16816(acc[1][0], a1.x, a1.y, a1.z, a1.w, w01.x, w01.y);
            mma16816(acc[0][1], a0.x, a0.y, a0.z, a0.w, w01.z, w01.w);
            mma16816(acc[1][1], a1.x, a1.y, a1.z, a1.w, w01.z, w01.w);
            mma16816(acc[0][2], a0.x, a0.y, a0.z, a0.w, w23.x, w23.y);
            mma16816(acc[1][2], a1.x, a1.y, a1.z, a1.w, w23.x, w23.y);
            mma16816(acc[0][3], a0.x, a0.y, a0.z, a0.w, w23.z, w23.w);
            mma16816(acc[1][3], a1.x, a1.y, a1.z, a1.w, w23.z, w23.w);
        }

        // deposit partials
        #pragma unroll
        for (int i = 0; i < 2; i++)
            #pragma unroll
            for (int g = 0; g < 4; g++)
                #pragma unroll
                for (int ci = 0; ci < 4; ci++)
                    sp_dep[(i * 16 + g * 4 + ci) * 32] = acc[i][g][ci];
        __syncthreads();   // all GEMM reads of W(s) complete -> buffer reusable

        // prefetch W(s+1) into the SMEM buffer; overlaps reduce+stores+barrier
        if (tid == 0 && s + 1 < NSTEP) {
            const char* Wn = (const char*)g_Wp
                           + (size_t)(((s + 1) & 3) * NCTA + cta) * WBYTES;
            mbar_expect_tx(mbar, WBYTES);
            #pragma unroll
            for (int c = 0; c < 4; c++)
                bulk_g2s(sbase + c * 32768, Wn + c * 32768, 32768, mbar);
        }

        // distributed reduce + cell update: each thread finalizes ONE cell
        float gate[4];
        #pragma unroll
        for (int g = 0; g < 4; g++) {
            float sum = 0.0f;
            #pragma unroll
            for (int ps = 0; ps < 8; ps++)
                sum += sp_red[((ps * 4) * 16 + g * 4 + di) * 32];
            gate[g] = sum;
        }

        float gi = gate[0] + bias[l][0];
        float gf = gate[1] + bias[l][1];
        float gg = gate[2] + bias[l][2];
        float go = gate[3] + bias[l][3];
        float ig = sigm(gi), fg = sigm(gf), og = sigm(go);
        float gt = tanh_fast(gg);
        float cn = fg * creg[l] + ig * gt;
        creg[l] = cn;
        float hn = og * tanh_fast(cn);
        __half hv = __float2half(hn);

        char* dstH = (char*)&g_A[p ^ 1][l][0];
        char* dstX = (l < LL - 1) ? (char*)&g_A[p][l + 1][0]
                                  : (char*)&g_A[p ^ 1][0][0];   // y feedback
        *(__half*)(dstH + (size_t)(wm2 * 128 + 64 + (cta >> 1)) * 512 + inblk_own) = hv;
        *(__half*)(dstX + (size_t)(wm2 * 128 + (cta >> 1)) * 512 + inblk_own) = hv;
        if (l == LL - 1)
            out[((size_t)r_own * TT + t) * HH + j_own] = hn;

        grid_sync();
    }
}

// ---------------------------------------------------------------------------
// kernel_launch: ONE persistent kernel (single graph node)
// inputs: x, h0, c0, W_ih, W_hh, b_ih, b_hh, seq_len
// ---------------------------------------------------------------------------
extern "C" void kernel_launch(void* const* d_in, const int* in_sizes, int n_in,
                              void* d_out, int out_size) {
    const float* x   = (const float*)d_in[0];
    const float* h0  = (const float*)d_in[1];
    const float* c0  = (const float*)d_in[2];
    const float* Wih = (const float*)d_in[3];
    const float* Whh = (const float*)d_in[4];
    const float* bih = (const float*)d_in[5];
    const float* bhh = (const float*)d_in[6];
    float* out = (float*)d_out;

    cudaFuncSetAttribute(lstm_main,
                         cudaFuncAttributeMaxDynamicSharedMemorySize, DYN_SMEM);
    lstm_main<<<NCTA, NTHR, DYN_SMEM>>>(x, h0, c0, Wih, Whh, bih, bhh, out);
}

// round 15
// speedup vs baseline: 1.4171x; 1.1224x over previous
#include <cuda_runtime.h>
#include <cuda_fp16.h>
#include <stdint.h>

// StackedUnidirLSTMDecoder: B=64, L=4, H=1024, T=128
#define BB    64
#define LL    4
#define HH    1024
#define TT    128
#define GG    4096
#define NCTA  128
#define NTHR  512             // 16 warps: (ks 0..7) x (mh 0..1); ks<4 = X, ks>=4 = H
#define NSTEP (TT * LL)       // 512
#define WBYTES 131072         // per-(l,cta) W slice: 128 kt x 1024 B
#define SPART_OFF  WBYTES
#define MBAR_OFF  (WBYTES + 65536)
#define DYN_SMEM  (WBYTES + 65536 + 64)    // 196672 B

// ---------------------------------------------------------------------------
// Device-global scratch
// ---------------------------------------------------------------------------
__device__ __align__(1024) __half g_Wp[(size_t)LL * NCTA * 128 * 512];
// A fragment blocks: g_A[p][l][mt=4][ktAll=128][512B]; ktAll<64 = X, >=64 = H
__device__ __align__(1024) __half g_A[2][LL][4 * 128 * 256];
__device__ float  g_bias[LL * GG];
__device__ unsigned g_bar_cnt, g_bar_gen;

// ---------------------------------------------------------------------------
// Full grid barrier (init only) + split arrive/wait pieces for the main loop
// ---------------------------------------------------------------------------
__device__ __forceinline__ void grid_sync_full() {
    __syncthreads();
    if (threadIdx.x == 0) {
        unsigned gen;
        asm volatile("ld.acquire.gpu.global.u32 %0, [%1];" : "=r"(gen) : "l"(&g_bar_gen));
        unsigned prev;
        asm volatile("atom.acq_rel.gpu.global.add.u32 %0, [%1], 1;"
                     : "=r"(prev) : "l"(&g_bar_cnt));
        if (prev == NCTA - 1) {
            asm volatile("st.relaxed.gpu.global.u32 [%0], %1;" :: "l"(&g_bar_cnt), "r"(0u));
            asm volatile("st.release.gpu.global.u32 [%0], %1;" :: "l"(&g_bar_gen), "r"(gen + 1u));
        } else {
            unsigned cur;
            do {
                asm volatile("ld.acquire.gpu.global.u32 %0, [%1];" : "=r"(cur) : "l"(&g_bar_gen));
            } while (cur == gen);
        }
    }
    __syncthreads();
}
__device__ __forceinline__ void bar_arrive() {
    unsigned prev;
    asm volatile("atom.acq_rel.gpu.global.add.u32 %0, [%1], 1;"
                 : "=r"(prev) : "l"(&g_bar_cnt));
    if (prev == NCTA - 1) {
        unsigned gen;
        asm volatile("ld.relaxed.gpu.global.u32 %0, [%1];" : "=r"(gen) : "l"(&g_bar_gen));
        asm volatile("st.relaxed.gpu.global.u32 [%0], %1;" :: "l"(&g_bar_cnt), "r"(0u));
        asm volatile("st.release.gpu.global.u32 [%0], %1;" :: "l"(&g_bar_gen), "r"(gen + 1u));
    }
}
__device__ __forceinline__ void bar_wait_ge(unsigned target) {
    unsigned cur;
    do {
        asm volatile("ld.acquire.gpu.global.u32 %0, [%1];" : "=r"(cur) : "l"(&g_bar_gen));
    } while ((int)(cur - target) < 0);
}

// ---------------------------------------------------------------------------
// mbarrier / bulk helpers (CTA-local)
// ---------------------------------------------------------------------------
__device__ __forceinline__ void mbar_init(uint32_t a, uint32_t cnt) {
    asm volatile("mbarrier.init.shared.b64 [%0], %1;" :: "r"(a), "r"(cnt) : "memory");
}
__device__ __forceinline__ void mbar_expect_tx(uint32_t a, uint32_t bytes) {
    asm volatile("mbarrier.arrive.expect_tx.shared.b64 _, [%0], %1;"
                 :: "r"(a), "r"(bytes) : "memory");
}
__device__ __forceinline__ void mbar_wait_acq(uint32_t a, uint32_t ph) {
    uint32_t done;
    do {
        asm volatile(
            "{\n\t.reg .pred p;\n\t"
            "mbarrier.try_wait.parity.acquire.cta.shared::cta.b64 p, [%1], %2, 0x989680;\n\t"
            "selp.b32 %0, 1, 0, p;\n\t}"
            : "=r"(done) : "r"(a), "r"(ph) : "memory");
    } while (!done);
}
__device__ __forceinline__ void bulk_g2s(uint32_t dst, const void* src, uint32_t bytes,
                                         uint32_t bar) {
    asm volatile(
        "cp.async.bulk.shared::cta.global.mbarrier::complete_tx::bytes "
        "[%0], [%1], %2, [%3];"
        :: "r"(dst), "l"(src), "r"(bytes), "r"(bar) : "memory");
}

__device__ __forceinline__ void mma16816(float* d,
                                         unsigned a0, unsigned a1, unsigned a2, unsigned a3,
                                         unsigned b0, unsigned b1) {
    asm volatile(
        "mma.sync.aligned.m16n8k16.row.col.f32.f16.f16.f32 "
        "{%0,%1,%2,%3},{%4,%5,%6,%7},{%8,%9},{%0,%1,%2,%3};\n"
        : "+f"(d[0]), "+f"(d[1]), "+f"(d[2]), "+f"(d[3])
        : "r"(a0), "r"(a1), "r"(a2), "r"(a3), "r"(b0), "r"(b1));
}
__device__ __forceinline__ float sigm(float v) { return 1.0f / (1.0f + __expf(-v)); }
__device__ __forceinline__ float tanh_fast(float v) {
    return 2.0f / (1.0f + __expf(-2.0f * v)) - 1.0f;
}

// GEMM for one step: 16 k-iters x 2 m-tiles, W from SMEM, A via LDG.cg;
// deposits partials. Same formula serves X-warps (ks<4) and H-warps (ks>=4).
__device__ __forceinline__ void gemm_deposit(int step, int aoff0, uint32_t wsm0,
                                             float* sp_dep) {
    const int l = step & 3;
    const int p = (step >> 2) & 1;
    const char* Ab0 = (const char*)&g_A[p][l][0] + aoff0;
    const char* Ab1 = Ab0 + 128 * 512;

    float acc[2][4][4];
    #pragma unroll
    for (int i = 0; i < 2; i++)
        #pragma unroll
        for (int a = 0; a < 4; a++)
            #pragma unroll
            for (int b = 0; b < 4; b++) acc[i][a][b] = 0.0f;

    #pragma unroll 4
    for (int kk = 0; kk < 16; kk++) {
        uint4 a0 = __ldcg((const uint4*)(Ab0 + (size_t)kk * 512));
        uint4 a1 = __ldcg((const uint4*)(Ab1 + (size_t)kk * 512));
        uint4 w01, w23;
        asm volatile("ld.shared.v4.u32 {%0,%1,%2,%3}, [%4];"
                     : "=r"(w01.x), "=r"(w01.y), "=r"(w01.z), "=r"(w01.w)
                     : "r"(wsm0 + (uint32_t)(kk * 1024)));
        asm volatile("ld.shared.v4.u32 {%0,%1,%2,%3}, [%4];"
                     : "=r"(w23.x), "=r"(w23.y), "=r"(w23.z), "=r"(w23.w)
                     : "r"(wsm0 + (uint32_t)(kk * 1024 + 512)));
        mma16816(acc[0][0], a0.x, a0.y, a0.z, a0.w, w01.x, w01.y);
        mma16816(acc[1][0], a1.x, a1.y, a1.z, a1.w, w01.x, w01.y);
        mma16816(acc[0][1], a0.x, a0.y, a0.z, a0.w, w01.z, w01.w);
        mma16816(acc[1][1], a1.x, a1.y, a1.z, a1.w, w01.z, w01.w);
        mma16816(acc[0][2], a0.x, a0.y, a0.z, a0.w, w23.x, w23.y);
        mma16816(acc[1][2], a1.x, a1.y, a1.z, a1.w, w23.x, w23.y);
        mma16816(acc[0][3], a0.x, a0.y, a0.z, a0.w, w23.z, w23.w);
        mma16816(acc[1][3], a1.x, a1.y, a1.z, a1.w, w23.z, w23.w);
    }
    #pragma unroll
    for (int i = 0; i < 2; i++)
        #pragma unroll
        for (int g = 0; g < 4; g++)
            #pragma unroll
            for (int ci = 0; ci < 4; ci++)
                sp_dep[(i * 16 + g * 4 + ci) * 32] = acc[i][g][ci];
}

// ---------------------------------------------------------------------------
// Persistent kernel with warp-role pipelining:
//   X-warps (tid<256, kt<64): wait global barrier -> GEMM-X(s) -> deposit.
//   H-warps (tid>=256, kt>=64, data 4 steps old): GEMM-H(s+1) + deposit at the
//   END of iter s, overlapping the global barrier arrival/release/stragglers.
// W(s) lives in a single SMEM buffer, bulk-prefetched during the reduce.
// ---------------------------------------------------------------------------
__global__ void __launch_bounds__(NTHR, 1)
lstm_main(const float* __restrict__ x,
          const float* __restrict__ h0,
          const float* __restrict__ c0,
          const float* __restrict__ Wih,
          const float* __restrict__ Whh,
          const float* __restrict__ b_ih,
          const float* __restrict__ b_hh,
          float* __restrict__ out) {
    extern __shared__ __align__(1024) char dsm[];
    uint32_t sbase;
    asm("{\n\t.reg .u64 t;\n\tcvta.to.shared.u64 t, %1;\n\tcvt.u32.u64 %0, t;\n\t}"
        : "=r"(sbase) : "l"(dsm));
    float* s_part = (float*)(dsm + SPART_OFF);
    const uint32_t mbar = sbase + MBAR_OFF;

    const int cta  = blockIdx.x;
    const int tid  = threadIdx.x;
    const int w    = tid >> 5;
    const int lane = tid & 31;
    const int ks   = w >> 1;          // 0..7; ks<4 X-warps, ks>=4 H-warps
    const int mh   = w & 1;

    // ---------------- phase 0: pack W into fragment order -------------------
    for (int v = cta * NTHR + tid; v < LL * NCTA * 128 * 32; v += NCTA * NTHR) {
        int plane = v & 31;
        int pkt   = (v >> 5) & 127;
        int pcta  = (v >> 12) & 127;
        int pl    = v >> 19;
        int c8 = plane >> 2;
        int kq = (plane & 3) * 2;
        #pragma unroll
        for (int np = 0; np < 2; np++)
            #pragma unroll
            for (int ntl = 0; ntl < 2; ntl++) {
                int nt = np * 2 + ntl;
                int n  = nt * 1024 + pcta * 8 + c8;
                __half vv[4];
                #pragma unroll
                for (int e = 0; e < 4; e++) {
                    int k = pkt * 16 + kq + (e & 1) + 8 * (e >> 1);
                    float wv = (k < HH) ? Wih[((size_t)pl * GG + n) * HH + k]
                                        : Whh[((size_t)pl * GG + n) * HH + (k - HH)];
                    vv[e] = __float2half(wv);
                }
                size_t off = ((((size_t)(pl * NCTA + pcta) * 128 + pkt) * 2 + np) * 32
                              + plane) * 8 + ntl * 4;
                *(uint2*)&g_Wp[off] = *(uint2*)vv;
            }
    }

    // ---------------- phase 1: init A (x, h0) + biases ----------------------
    for (int v = cta * NTHR + tid; v < LL * BB * HH; v += NCTA * NTHR) {
        if (v < LL * GG) g_bias[v] = b_ih[v] + b_hh[v];
        int k = v & (HH - 1);
        int r = (v >> 10) & (BB - 1);
        int l = v >> 16;
        int mt    = r >> 4;
        int lane2 = (r & 7) * 4 + ((k & 7) >> 1);
        int reg   = ((r & 15) >> 3) + 2 * ((k & 15) >> 3);
        int inblk = lane2 * 8 + reg * 2 + (k & 1);
        g_A[0][l][(mt * 128 + 64 + (k >> 4)) * 256 + inblk] = __float2half(h0[v]);
        if (l == 0)
            g_A[0][0][(mt * 128 + (k >> 4)) * 256 + inblk] = __float2half(x[r * HH + k]);
    }
    if (tid == 0) mbar_init(mbar, 1);
    grid_sync_full();   // pack + init globally visible; mbar initialized

    unsigned gen_base = 0;
    if (tid == 0) {
        asm volatile("ld.acquire.gpu.global.u32 %0, [%1];"
                     : "=r"(gen_base) : "l"(&g_bar_gen));
    }

    // ---------------- per-thread cell ownership -----------------------------
    const int ks2   = w >> 2;
    const int wm2   = w & 3;
    const int qrow2 = lane >> 1;
    const int jj    = (lane & 1) * 4 + ks2;
    const int qrowp = qrow2 & 7;
    const int hh2   = qrow2 >> 3;
    const int tqp   = jj >> 1;
    const int u     = jj & 1;
    const int lanep = qrowp * 4 + tqp;
    const int di    = hh2 * 2 + u;
    const int r_own = wm2 * 16 + qrow2;
    const int j_own = cta * 8 + jj;

    float bias[LL][4], creg[LL];
    #pragma unroll
    for (int l = 0; l < LL; l++) {
        #pragma unroll
        for (int g = 0; g < 4; g++)
            bias[l][g] = g_bias[l * GG + g * 1024 + j_own];
        creg[l] = c0[((size_t)l * BB + r_own) * HH + j_own];
    }

    const char* __restrict__ Wcta = (const char*)g_Wp + (size_t)cta * WBYTES;
    const int aoff0 = ((mh * 2) * 128 + ks * 16) * 512 + lane * 16;
    const uint32_t wsm0 = sbase + (uint32_t)((ks * 16) * 1024 + lane * 16);
    const int inblk_own = lanep * 16 + (cta & 1) * 8 + hh2 * 4 + u * 2;
    float* sp_dep = s_part + ((ks * 4 + mh * 2) * 16) * 32 + lane;
    const float* sp_red = s_part + (wm2 * 16) * 32 + lanep;

    // prologue: prefetch W(0); H-warps pre-compute GEMM-H(0) + deposit
    if (tid == 0) {
        asm volatile("fence.proxy.async;" ::: "memory");
        mbar_expect_tx(mbar, WBYTES);
        #pragma unroll
        for (int c = 0; c < 4; c++)
            bulk_g2s(sbase + c * 32768, Wcta + c * 32768, 32768, mbar);
    }
    if (tid >= 256) {
        mbar_wait_acq(mbar, 0);
        gemm_deposit(0, aoff0, wsm0, sp_dep);
    }

    // ---------------- phase 2: 512 sequential cell-steps --------------------
    for (int s = 0; s < NSTEP; s++) {
        const int l = s & 3;
        const int t = s >> 2;
        const int p = t & 1;

        if (tid < 256) {               // X-warps: gated on global barrier
            if (tid == 0) bar_wait_ge(gen_base + (unsigned)s);
            asm volatile("bar.sync 1, 256;" ::: "memory");
            mbar_wait_acq(mbar, (unsigned)s & 1);
            gemm_deposit(s, aoff0, wsm0, sp_dep);
        }
        __syncthreads();               // all partials(s) ready; W(s) reads done

        // prefetch W(s+1) during reduce + barrier window
        if (tid == 0 && s + 1 < NSTEP) {
            const char* Wn = (const char*)g_Wp
                           + (size_t)(((s + 1) & 3) * NCTA + cta) * WBYTES;
            mbar_expect_tx(mbar, WBYTES);
            #pragma unroll
            for (int c = 0; c < 4; c++)
                bulk_g2s(sbase + c * 32768, Wn + c * 32768, 32768, mbar);
        }

        // distributed reduce + cell update: each thread finalizes ONE cell
        float gate[4];
        #pragma unroll
        for (int g = 0; g < 4; g++) {
            float sum = 0.0f;
            #pragma unroll
            for (int ps = 0; ps < 8; ps++)
                sum += sp_red[((ps * 4) * 16 + g * 4 + di) * 32];
            gate[g] = sum;
        }

        float gi = gate[0] + bias[l][0];
        float gf = gate[1] + bias[l][1];
        float gg = gate[2] + bias[l][2];
        float go = gate[3] + bias[l][3];
        float ig = sigm(gi), fg = sigm(gf), og = sigm(go);
        float gt = tanh_fast(gg);
        float cn = fg * creg[l] + ig * gt;
        creg[l] = cn;
        float hn = og * tanh_fast(cn);
        __half hv = __float2half(hn);

        char* dstH = (char*)&g_A[p ^ 1][l][0];
        char* dstX = (l < LL - 1) ? (char*)&g_A[p][l + 1][0]
                                  : (char*)&g_A[p ^ 1][0][0];   // y feedback
        *(__half*)(dstH + (size_t)(wm2 * 128 + 64 + (cta >> 1)) * 512 + inblk_own) = hv;
        *(__half*)(dstX + (size_t)(wm2 * 128 + (cta >> 1)) * 512 + inblk_own) = hv;
        if (l == LL - 1)
            out[((size_t)r_own * TT + t) * HH + j_own] = hn;

        __syncthreads();               // stores + reduce-reads(s) complete

        if (tid == 0 && s + 1 < NSTEP) bar_arrive();   // release other CTAs early

        if (tid >= 256 && s + 1 < NSTEP) {   // H-warps run ahead: step s+1
            mbar_wait_acq(mbar, (unsigned)(s + 1) & 1);
            gemm_deposit(s + 1, aoff0, wsm0, sp_dep);
        }
    }
}

// ---------------------------------------------------------------------------
// kernel_launch: ONE persistent kernel (single graph node)
// inputs: x, h0, c0, W_ih, W_hh, b_ih, b_hh, seq_len
// ---------------------------------------------------------------------------
extern "C" void kernel_launch(void* const* d_in, const int* in_sizes, int n_in,
                              void* d_out, int out_size) {
    const float* x   = (const float*)d_in[0];
    const float* h0  = (const float*)d_in[1];
    const float* c0  = (const float*)d_in[2];
    const float* Wih = (const float*)d_in[3];
    const float* Whh = (const float*)d_in[4];
    const float* bih = (const float*)d_in[5];
    const float* bhh = (const float*)d_in[6];
    float* out = (float*)d_out;

    cudaFuncSetAttribute(lstm_main,
                         cudaFuncAttributeMaxDynamicSharedMemorySize, DYN_SMEM);
    lstm_main<<<NCTA, NTHR, DYN_SMEM>>>(x, h0, c0, Wih, Whh, bih, bhh, out);
}